// round 16
// baseline (speedup 1.0000x reference)
#include <cuda_runtime.h>
#include <math.h>

#define Bc   64
#define Tc   512
#define TPB  512
#define NCTA 128

// -------------------- scratch (static device globals; no allocation) --------------------
__device__ float g_xg[Bc * Tc * 2048];     // input-projection gates (reused per layer)
__device__ float g_seq[Bc * Tc * 256];     // y1 / y3 sequence buffer (reused)
__device__ float g_h[2 * Bc * 512];        // ping-pong recurrent h state
__device__ float g_h0[Bc * 512];           // encoder2 final h
__device__ float g_g0[Bc * 1024];          // decoder1 constant pre-activation gates
__device__ unsigned g_flags[NCTA];         // per-CTA step flags (memset 0 before each layer)

// -------------------- packed f32x2 fma --------------------
__device__ __forceinline__ void ffma2(unsigned long long& a,
                                      unsigned long long x, unsigned long long y) {
    asm("fma.rn.f32x2 %0, %1, %2, %0;" : "+l"(a) : "l"(x), "l"(y));
}
__device__ __forceinline__ float f2sum(unsigned long long a) {
    return __uint_as_float((unsigned)a) + __uint_as_float((unsigned)(a >> 32));
}

// -------------------- flag-vector grid barrier (no atomics, no hot line) ----------------
// Each CTA stores step counter 'bar' to its own flag (release). Warp 0 polls all 128
// flags (32 lanes x v4) until every flag >= bar. Flags zeroed before kernel launch.
__device__ __forceinline__ void flag_barrier(int tid, unsigned bar) {
    __syncthreads();   // all CTA writes done before signaling
    if (tid == 0) {
        asm volatile("st.release.gpu.global.u32 [%0], %1;"
                     :: "l"(&g_flags[blockIdx.x]), "r"(bar) : "memory");
    }
    if (tid < 32) {
        const uint4* fp = (const uint4*)g_flags + tid;   // 32 lanes x 4 = 128 flags
        unsigned ok;
        do {
            uint4 f;
            asm volatile("ld.volatile.global.v4.u32 {%0,%1,%2,%3}, [%4];"
                         : "=r"(f.x), "=r"(f.y), "=r"(f.z), "=r"(f.w) : "l"(fp));
            ok = (f.x >= bar) & (f.y >= bar) & (f.z >= bar) & (f.w >= bar);
        } while (__all_sync(0xffffffffu, ok) == 0);
        __threadfence();   // acquire: order subsequent h reads after flag observation
    }
    __syncthreads();
}

// -------------------- tiled fp32 GEMM: Y[M,N] = X[M,K] @ W[N,K]^T + bias ----------------
__global__ void __launch_bounds__(256) gemm_bias(
    const float* __restrict__ X, const float* __restrict__ W,
    const float* __restrict__ bias, float* __restrict__ Y,
    int M, int N, int K, const int* __restrict__ lengths)
{
    const int BM = 64, BN = 64, BK = 16;
    int n0 = blockIdx.x * BN;
    int m0 = blockIdx.y * BM;
    if (lengths) {
        int b = m0 >> 9, t0 = m0 & 511;
        if (t0 >= lengths[b]) return;   // rows past length never read downstream
    }
    __shared__ float Xs[BK][BM + 4];
    __shared__ float Ws[BK][BN + 4];
    int tid = threadIdx.x;
    int tx = tid & 15, ty = tid >> 4;
    int lm = tid >> 2, lk4 = (tid & 3) * 4;

    float acc[4][4];
#pragma unroll
    for (int i = 0; i < 4; i++)
#pragma unroll
        for (int j = 0; j < 4; j++) acc[i][j] = 0.f;

    for (int k0 = 0; k0 < K; k0 += BK) {
        float4 xv = *(const float4*)&X[(size_t)(m0 + lm) * K + k0 + lk4];
        float4 wv = *(const float4*)&W[(size_t)(n0 + lm) * K + k0 + lk4];
        __syncthreads();
        Xs[lk4 + 0][lm] = xv.x; Xs[lk4 + 1][lm] = xv.y;
        Xs[lk4 + 2][lm] = xv.z; Xs[lk4 + 3][lm] = xv.w;
        Ws[lk4 + 0][lm] = wv.x; Ws[lk4 + 1][lm] = wv.y;
        Ws[lk4 + 2][lm] = wv.z; Ws[lk4 + 3][lm] = wv.w;
        __syncthreads();
#pragma unroll
        for (int k = 0; k < BK; k++) {
            float4 xr = *(const float4*)&Xs[k][ty * 4];
            float4 wr = *(const float4*)&Ws[k][tx * 4];
            float xa[4] = {xr.x, xr.y, xr.z, xr.w};
            float wa[4] = {wr.x, wr.y, wr.z, wr.w};
#pragma unroll
            for (int i = 0; i < 4; i++)
#pragma unroll
                for (int j = 0; j < 4; j++) acc[i][j] += xa[i] * wa[j];
        }
    }
    float bb[4];
#pragma unroll
    for (int j = 0; j < 4; j++) bb[j] = bias[n0 + tx * 4 + j];
#pragma unroll
    for (int i = 0; i < 4; i++) {
        size_t row = (size_t)(m0 + ty * 4 + i) * N + n0 + tx * 4;
#pragma unroll
        for (int j = 0; j < 4; j++) Y[row + j] = acc[i][j] + bb[j];
    }
}

// -------------------- persistent recurrent LSTM layer --------------------
// CTA owns U hidden units (4U gate rows, weights in smem). Ping-pong global h buffers.
// Per step: prefetch xg, stage h(read-buf) via __ldcg, packed-f32x2 gate dots (S slices),
// smem reduce, pointwise, write h(write-buf), flag barrier.
template <int H, int U, int S, bool WRITE_Y, bool CONST_IN>
__global__ void __launch_bounds__(TPB, 1) lstm_rec(
    const float* __restrict__ xg,      // [B,T,4H] (or [B,4H] if CONST_IN)
    const float* __restrict__ whh,     // [4H,H]
    const int*   __restrict__ lengths, // [B]
    float*       __restrict__ hbuf,    // [2,B,H] ping-pong h state
    float*       __restrict__ yout)    // WRITE_Y: [B,T,H]; else final h -> [B,H]
{
    constexpr int Hp = H + 4;
    constexpr int R = 4 * U;
    constexpr int TASKS = Bc * U;
    static_assert(TASKS * S == TPB, "task/slice mismatch");

    extern __shared__ char smem_raw[];
    float* Ws   = (float*)smem_raw;          // R * Hp
    float* hs   = Ws + R * Hp;               // 64 * Hp
    float* cs   = hs + Bc * Hp;              // TASKS
    float* part = cs + TASKS;                // 4 * TPB
    int*   ls   = (int*)(part + 4 * TPB);    // 64

    const int tid = threadIdx.x;
    const int j0 = blockIdx.x * U;

    if (tid < Bc) ls[tid] = lengths[tid];
    for (int idx = tid; idx < R * (H / 4); idx += TPB) {
        int r = idx / (H / 4), kk = idx % (H / 4);
        int g = r / U, u = r % U;
        float4 v = *(const float4*)&whh[(size_t)(g * H + j0 + u) * H + kk * 4];
        *(float4*)&Ws[r * Hp + kk * 4] = v;
    }
    for (int idx = tid; idx < TASKS; idx += TPB) cs[idx] = 0.f;
    for (int idx = tid; idx < Bc * U; idx += TPB)
        hbuf[(idx / U) * H + j0 + (idx % U)] = 0.f;   // zero buffer 0 (own units)
    flag_barrier(tid, 1u);

    const int tt = tid % TASKS;
    const int sl = tid / TASKS;
    const int b  = tt / U;
    const int u  = tt % U;
    const int j  = j0 + u;
    const float* w0 = &Ws[(0 * U + u) * Hp];
    const float* w1 = &Ws[(1 * U + u) * Hp];
    const float* w2 = &Ws[(2 * U + u) * Hp];
    const float* w3 = &Ws[(3 * U + u) * Hp];
    const float* hrow = &hs[b * Hp];
    constexpr int KS = H / S;
    const int kb = sl * KS;

    for (int t = 0; t < Tc; ++t) {
        const float* hr = hbuf + (size_t)(t & 1) * Bc * H;        // read buffer
        float*       hw = hbuf + (size_t)((t + 1) & 1) * Bc * H;  // write buffer
        const bool valid = (t < ls[b]);

        // prefetch xg (DRAM) before h staging to overlap latency
        float x0 = 0.f, x1 = 0.f, x2 = 0.f, x3 = 0.f;
        if (sl == 0 && valid) {
            const float* xr = CONST_IN ? &xg[(size_t)b * 4 * H]
                                       : &xg[((size_t)b * Tc + t) * 4 * H];
            x0 = xr[0 * H + j]; x1 = xr[1 * H + j];
            x2 = xr[2 * H + j]; x3 = xr[3 * H + j];
        }
        // stage h into smem (L2 reads; bypass non-coherent L1)
        for (int idx = tid; idx < Bc * (H / 4); idx += TPB) {
            int bb = idx / (H / 4), kk = idx % (H / 4);
            *(float4*)&hs[bb * Hp + kk * 4] = __ldcg((const float4*)&hr[bb * H + kk * 4]);
        }
        __syncthreads();

        unsigned long long p0 = 0, p1 = 0, p2 = 0, p3 = 0;
        if (valid) {
#pragma unroll 4
            for (int k = kb; k < kb + KS; k += 4) {
                ulonglong2 hv = *(const ulonglong2*)&hrow[k];
                ulonglong2 q0 = *(const ulonglong2*)&w0[k];
                ulonglong2 q1 = *(const ulonglong2*)&w1[k];
                ulonglong2 q2 = *(const ulonglong2*)&w2[k];
                ulonglong2 q3 = *(const ulonglong2*)&w3[k];
                ffma2(p0, hv.x, q0.x); ffma2(p1, hv.x, q1.x);
                ffma2(p2, hv.x, q2.x); ffma2(p3, hv.x, q3.x);
                ffma2(p0, hv.y, q0.y); ffma2(p1, hv.y, q1.y);
                ffma2(p2, hv.y, q2.y); ffma2(p3, hv.y, q3.y);
            }
        }
        if (S > 1) {
            part[tid * 4 + 0] = f2sum(p0); part[tid * 4 + 1] = f2sum(p1);
            part[tid * 4 + 2] = f2sum(p2); part[tid * 4 + 3] = f2sum(p3);
            __syncthreads();
        }
        if (tid < TASKS) {
            float hn;
            if (valid) {
                float a0, a1, a2, a3;
                if (S > 1) {
                    a0 = part[tid * 4 + 0]; a1 = part[tid * 4 + 1];
                    a2 = part[tid * 4 + 2]; a3 = part[tid * 4 + 3];
#pragma unroll
                    for (int s2 = 1; s2 < S; ++s2) {
                        int o = (s2 * TASKS + tid) * 4;
                        a0 += part[o + 0]; a1 += part[o + 1];
                        a2 += part[o + 2]; a3 += part[o + 3];
                    }
                } else {
                    a0 = f2sum(p0); a1 = f2sum(p1); a2 = f2sum(p2); a3 = f2sum(p3);
                }
                float gi = a0 + x0, gf = a1 + x1, gg = a2 + x2, go = a3 + x3;
                float ig = 1.f / (1.f + expf(-gi));
                float fg = 1.f / (1.f + expf(-gf));
                float gv = tanhf(gg);
                float og = 1.f / (1.f + expf(-go));
                float c  = fg * cs[tt] + ig * gv;
                cs[tt] = c;
                hn = og * tanhf(c);
                if (WRITE_Y) yout[((size_t)b * Tc + t) * H + j] = hn;
            } else {
                hn = hrow[j];   // frozen: carry forward staged value
            }
            hw[b * H + j] = hn;
        }
        flag_barrier(tid, (unsigned)(t + 2));
    }

    if (!WRITE_Y) {   // final frozen h lives in buffer (Tc & 1) = 0
        for (int idx = tid; idx < Bc * U; idx += TPB) {
            int bb = idx / U, uu = idx % U;
            yout[bb * H + j0 + uu] = hbuf[bb * H + j0 + uu];
        }
    }
}

// -------------------- classifier head --------------------
__global__ void __launch_bounds__(256) head_kernel(
    const float* __restrict__ h0,
    const float* __restrict__ lw1, const float* __restrict__ lb1,
    const float* __restrict__ lw2, const float* __restrict__ lb2,
    float* __restrict__ outp)
{
    __shared__ float hv[512];
    __shared__ float hid[256];
    __shared__ float lg[2];
    int bidx = blockIdx.x, tid = threadIdx.x;
    hv[tid]       = h0[bidx * 512 + tid];
    hv[tid + 256] = h0[bidx * 512 + 256 + tid];
    __syncthreads();
    float acc = lb1[tid];
    const float* wr = &lw1[tid * 512];
#pragma unroll 4
    for (int k = 0; k < 512; k += 4) {
        float4 w = *(const float4*)&wr[k];
        acc += w.x * hv[k] + w.y * hv[k + 1] + w.z * hv[k + 2] + w.w * hv[k + 3];
    }
    hid[tid] = fmaxf(acc, 0.f);
    __syncthreads();
    if (tid < 64) {
        int c = tid >> 5, lane = tid & 31;
        float p = 0.f;
        for (int k = lane; k < 256; k += 32) p += hid[k] * lw2[c * 256 + k];
#pragma unroll
        for (int off = 16; off; off >>= 1) p += __shfl_down_sync(0xffffffffu, p, off);
        if (lane == 0) lg[c] = p + lb2[c];
    }
    __syncthreads();
    if (tid == 0) {
        float m = fmaxf(lg[0], lg[1]);
        float lse = m + logf(expf(lg[0] - m) + expf(lg[1] - m));
        outp[bidx * 2 + 0] = lg[0] - lse;
        outp[bidx * 2 + 1] = lg[1] - lse;
    }
}

// -------------------- launcher --------------------
static inline int lstm_smem_bytes(int H, int U) {
    int Hp = H + 4, R = 4 * U, TASKS = Bc * U;
    return 4 * (R * Hp + Bc * Hp + TASKS + 4 * TPB) + Bc * 4 + 16;
}

extern "C" void kernel_launch(void* const* d_in, const int* in_sizes, int n_in,
                              void* d_out, int out_size) {
    const float* x       = (const float*)d_in[0];
    const int*   lengths = (const int*)  d_in[1];
    const float* e1_wih  = (const float*)d_in[2];
    const float* e1_whh  = (const float*)d_in[3];
    const float* e1_b    = (const float*)d_in[4];
    const float* e2_wih  = (const float*)d_in[5];
    const float* e2_whh  = (const float*)d_in[6];
    const float* e2_b    = (const float*)d_in[7];
    const float* d1_wih  = (const float*)d_in[8];
    const float* d1_whh  = (const float*)d_in[9];
    const float* d1_b    = (const float*)d_in[10];
    const float* d2_wih  = (const float*)d_in[11];
    const float* d2_whh  = (const float*)d_in[12];
    const float* d2_b    = (const float*)d_in[13];
    const float* lw1     = (const float*)d_in[14];
    const float* lb1     = (const float*)d_in[15];
    const float* lw2     = (const float*)d_in[16];
    const float* lb2     = (const float*)d_in[17];
    float* out = (float*)d_out;

    float *xgp, *seqp, *hp, *h0p, *g0p;
    unsigned* flp;
    cudaGetSymbolAddress((void**)&xgp,  g_xg);
    cudaGetSymbolAddress((void**)&seqp, g_seq);
    cudaGetSymbolAddress((void**)&hp,   g_h);
    cudaGetSymbolAddress((void**)&h0p,  g_h0);
    cudaGetSymbolAddress((void**)&g0p,  g_g0);
    cudaGetSymbolAddress((void**)&flp,  g_flags);

    const int SMEM_E1 = lstm_smem_bytes(256, 2);
    const int SMEM_E2 = lstm_smem_bytes(512, 4);
    const int SMEM_D2 = lstm_smem_bytes(128, 1);
    cudaFuncSetAttribute((const void*)lstm_rec<256, 2, 4, true,  false>,
                         cudaFuncAttributeMaxDynamicSharedMemorySize, SMEM_E1);
    cudaFuncSetAttribute((const void*)lstm_rec<512, 4, 2, false, false>,
                         cudaFuncAttributeMaxDynamicSharedMemorySize, SMEM_E2);
    cudaFuncSetAttribute((const void*)lstm_rec<256, 2, 4, true,  true>,
                         cudaFuncAttributeMaxDynamicSharedMemorySize, SMEM_E1);
    cudaFuncSetAttribute((const void*)lstm_rec<128, 1, 8, true,  false>,
                         cudaFuncAttributeMaxDynamicSharedMemorySize, SMEM_D2);

    const int M = Bc * Tc;

    cudaMemsetAsync(d_out, 0, (size_t)out_size * sizeof(float));

    // encoder 1
    gemm_bias<<<dim3(1024 / 64, M / 64), 256>>>(x, e1_wih, e1_b, xgp, M, 1024, 128, lengths);
    cudaMemsetAsync(flp, 0, NCTA * sizeof(unsigned));
    lstm_rec<256, 2, 4, true, false><<<NCTA, TPB, SMEM_E1>>>(xgp, e1_whh, lengths, hp, seqp);

    // encoder 2
    gemm_bias<<<dim3(2048 / 64, M / 64), 256>>>(seqp, e2_wih, e2_b, xgp, M, 2048, 256, lengths);
    cudaMemsetAsync(flp, 0, NCTA * sizeof(unsigned));
    lstm_rec<512, 4, 2, false, false><<<NCTA, TPB, SMEM_E2>>>(xgp, e2_whh, lengths, hp, h0p);

    // decoder 1 (constant per-batch input)
    gemm_bias<<<dim3(1024 / 64, 1), 256>>>(h0p, d1_wih, d1_b, g0p, Bc, 1024, 512, nullptr);
    cudaMemsetAsync(flp, 0, NCTA * sizeof(unsigned));
    lstm_rec<256, 2, 4, true, true><<<NCTA, TPB, SMEM_E1>>>(g0p, d1_whh, lengths, hp, seqp);

    // decoder 2 -> d_out
    gemm_bias<<<dim3(512 / 64, M / 64), 256>>>(seqp, d2_wih, d2_b, xgp, M, 512, 256, lengths);
    cudaMemsetAsync(flp, 0, NCTA * sizeof(unsigned));
    lstm_rec<128, 1, 8, true, false><<<NCTA, TPB, SMEM_D2>>>(xgp, d2_whh, lengths, hp, out);

    // classifier head
    head_kernel<<<Bc, 256>>>(h0p, lw1, lb1, lw2, lb2, out + (size_t)out_size - 2 * Bc);
}

// round 17
// speedup vs baseline: 1.4561x; 1.4561x over previous
#include <cuda_runtime.h>
#include <math.h>

#define Bc   64
#define Tc   512
#define TPB  512
#define NCTA 128
#define NGRP 16

// -------------------- scratch (static device globals; no allocation) --------------------
__device__ float g_xg[Bc * Tc * 2048];     // input-projection gates (reused per layer)
__device__ float g_seq[Bc * Tc * 256];     // y1 / y3 sequence buffer (reused)
__device__ float g_h[2 * Bc * 512];        // ping-pong recurrent h state
__device__ float g_h0[Bc * 512];           // encoder2 final h
__device__ float g_g0[Bc * 1024];          // decoder1 constant pre-activation gates
__device__ unsigned g_sync[2 * NGRP * 32]; // [g*32]: arrive counters; [(16+g)*32]: release words

// -------------------- packed f32x2 fma --------------------
__device__ __forceinline__ void ffma2(unsigned long long& a,
                                      unsigned long long x, unsigned long long y) {
    asm("fma.rn.f32x2 %0, %1, %2, %0;" : "+l"(a) : "l"(x), "l"(y));
}
__device__ __forceinline__ float f2lo(unsigned long long a) {
    return __uint_as_float((unsigned)a);
}
__device__ __forceinline__ float f2hi(unsigned long long a) {
    return __uint_as_float((unsigned)(a >> 32));
}
__device__ __forceinline__ float f2sum(unsigned long long a) {
    return f2lo(a) + f2hi(a);
}
__device__ __forceinline__ unsigned long long fdup(float w) {
    unsigned long long r;
    asm("mov.b64 %0, {%1,%1};" : "=l"(r) : "f"(w));
    return r;
}

// -------------------- barrier v3: distributed arrive / root aggregate / distributed release
// 128 CTAs = 16 groups x 8. Arrive: red.release to group counter (own line). Root warp
// (CTA 0) polls 16 counters, then stores phase to 16 release lines; each CTA polls only
// its group's release line (8 pollers/line). Counters monotonic; memset 0 per layer.
__device__ __forceinline__ void bar_arrive(int tid) {
    __syncthreads();                       // all CTA work done
    if (tid == 0) {
        __threadfence();                   // make this CTA's global writes gpu-visible
        asm volatile("red.release.gpu.global.add.u32 [%0], 1;"
                     :: "l"(&g_sync[(blockIdx.x >> 3) << 5]) : "memory");
    }
}
__device__ __forceinline__ void bar_wait(int tid, unsigned bar) {
    if (blockIdx.x == 0 && tid < 32) {     // root warp aggregates
        unsigned tgt = bar * 8u;
        const unsigned* gp = &g_sync[(tid & 15) << 5];
        unsigned v;
        do {
            asm volatile("ld.acquire.gpu.global.u32 %0, [%1];" : "=r"(v) : "l"(gp));
        } while (__all_sync(0xffffffffu, v >= tgt) == 0);
        if (tid < 16)
            asm volatile("st.release.gpu.global.u32 [%0], %1;"
                         :: "l"(&g_sync[(16 + tid) << 5]), "r"(bar) : "memory");
    }
    if (tid == 0) {
        const unsigned* rp = &g_sync[(16 + (blockIdx.x >> 3)) << 5];
        unsigned v;
        do {
            asm volatile("ld.acquire.gpu.global.u32 %0, [%1];" : "=r"(v) : "l"(rp));
        } while (v < bar);
        __threadfence();
    }
    __syncthreads();
}

// -------------------- tiled fp32 GEMM (f32x2 inner): Y[M,N] = X[M,K] @ W[N,K]^T + bias ----
__global__ void __launch_bounds__(256) gemm_bias(
    const float* __restrict__ X, const float* __restrict__ W,
    const float* __restrict__ bias, float* __restrict__ Y,
    int M, int N, int K, const int* __restrict__ lengths)
{
    const int BM = 64, BN = 64, BK = 16;
    int n0 = blockIdx.x * BN;
    int m0 = blockIdx.y * BM;
    if (lengths) {
        int b = m0 >> 9, t0 = m0 & 511;
        if (t0 >= lengths[b]) return;   // rows past length never read downstream
    }
    __shared__ float Xs[BK][BM + 4];
    __shared__ float Ws[BK][BN + 4];
    int tid = threadIdx.x;
    int tx = tid & 15, ty = tid >> 4;
    int lm = tid >> 2, lk4 = (tid & 3) * 4;

    // acc2[ipair][j]: packed rows (ty*4+2*ipair, ty*4+2*ipair+1), column n0+tx*4+j
    unsigned long long acc2[2][4];
#pragma unroll
    for (int i = 0; i < 2; i++)
#pragma unroll
        for (int j = 0; j < 4; j++) acc2[i][j] = 0ull;

    for (int k0 = 0; k0 < K; k0 += BK) {
        float4 xv = *(const float4*)&X[(size_t)(m0 + lm) * K + k0 + lk4];
        float4 wv = *(const float4*)&W[(size_t)(n0 + lm) * K + k0 + lk4];
        __syncthreads();
        Xs[lk4 + 0][lm] = xv.x; Xs[lk4 + 1][lm] = xv.y;
        Xs[lk4 + 2][lm] = xv.z; Xs[lk4 + 3][lm] = xv.w;
        Ws[lk4 + 0][lm] = wv.x; Ws[lk4 + 1][lm] = wv.y;
        Ws[lk4 + 2][lm] = wv.z; Ws[lk4 + 3][lm] = wv.w;
        __syncthreads();
#pragma unroll
        for (int k = 0; k < BK; k++) {
            ulonglong2 xp = *(const ulonglong2*)&Xs[k][ty * 4];  // pairs {x0,x1},{x2,x3}
            float4 wr = *(const float4*)&Ws[k][tx * 4];
            unsigned long long wd0 = fdup(wr.x), wd1 = fdup(wr.y);
            unsigned long long wd2 = fdup(wr.z), wd3 = fdup(wr.w);
            ffma2(acc2[0][0], xp.x, wd0); ffma2(acc2[1][0], xp.y, wd0);
            ffma2(acc2[0][1], xp.x, wd1); ffma2(acc2[1][1], xp.y, wd1);
            ffma2(acc2[0][2], xp.x, wd2); ffma2(acc2[1][2], xp.y, wd2);
            ffma2(acc2[0][3], xp.x, wd3); ffma2(acc2[1][3], xp.y, wd3);
        }
    }
    float bb[4];
#pragma unroll
    for (int j = 0; j < 4; j++) bb[j] = bias[n0 + tx * 4 + j];
#pragma unroll
    for (int ip = 0; ip < 2; ip++) {
        size_t r0 = (size_t)(m0 + ty * 4 + 2 * ip) * N + n0 + tx * 4;
        size_t r1 = r0 + N;
#pragma unroll
        for (int j = 0; j < 4; j++) {
            Y[r0 + j] = f2lo(acc2[ip][j]) + bb[j];
            Y[r1 + j] = f2hi(acc2[ip][j]) + bb[j];
        }
    }
}

// -------------------- persistent recurrent LSTM layer --------------------
// CTA owns U hidden units (4U gate rows, weights in smem). Ping-pong global h buffers.
// Per step: stage h (ldcg), packed-f32x2 gate dots (S k-slices), smem reduce, pointwise,
// write h, arrive -> prefetch next xg -> wait.
template <int H, int U, int S, bool WRITE_Y, bool CONST_IN>
__global__ void __launch_bounds__(TPB, 1) lstm_rec(
    const float* __restrict__ xg,      // [B,T,4H] (or [B,4H] if CONST_IN)
    const float* __restrict__ whh,     // [4H,H]
    const int*   __restrict__ lengths, // [B]
    float*       __restrict__ hbuf,    // [2,B,H] ping-pong h state
    float*       __restrict__ yout)    // WRITE_Y: [B,T,H]; else final h -> [B,H]
{
    constexpr int Hp = H + 4;
    constexpr int R = 4 * U;
    constexpr int TASKS = Bc * U;
    static_assert(TASKS * S == TPB, "task/slice mismatch");

    extern __shared__ char smem_raw[];
    float* Ws   = (float*)smem_raw;          // R * Hp
    float* hs   = Ws + R * Hp;               // 64 * Hp
    float* cs   = hs + Bc * Hp;               // TASKS
    float* part = cs + TASKS;                 // 4 * TPB
    int*   ls   = (int*)(part + 4 * TPB);     // 64

    const int tid = threadIdx.x;
    const int j0 = blockIdx.x * U;

    if (tid < Bc) ls[tid] = lengths[tid];
    for (int idx = tid; idx < R * (H / 4); idx += TPB) {
        int r = idx / (H / 4), kk = idx % (H / 4);
        int g = r / U, u = r % U;
        float4 v = *(const float4*)&whh[(size_t)(g * H + j0 + u) * H + kk * 4];
        *(float4*)&Ws[r * Hp + kk * 4] = v;
    }
    for (int idx = tid; idx < TASKS; idx += TPB) cs[idx] = 0.f;
    for (int idx = tid; idx < Bc * U; idx += TPB)
        hbuf[(idx / U) * H + j0 + (idx % U)] = 0.f;   // zero buffer 0 (own units)

    const int tt = tid % TASKS;
    const int sl = tid / TASKS;
    const int b  = tt / U;
    const int u  = tt % U;
    const int j  = j0 + u;
    const float* w0 = &Ws[(0 * U + u) * Hp];
    const float* w1 = &Ws[(1 * U + u) * Hp];
    const float* w2 = &Ws[(2 * U + u) * Hp];
    const float* w3 = &Ws[(3 * U + u) * Hp];
    const float* hrow = &hs[b * Hp];
    constexpr int KS = H / S;
    const int kb = sl * KS;

    bar_arrive(tid);
    // prefetch xg for t=0 while waiting
    float x0 = 0.f, x1 = 0.f, x2 = 0.f, x3 = 0.f;
    if (sl == 0) {
        const float* xr = CONST_IN ? &xg[(size_t)b * 4 * H] : &xg[(size_t)b * Tc * 4 * H];
        x0 = xr[0 * H + j]; x1 = xr[1 * H + j];
        x2 = xr[2 * H + j]; x3 = xr[3 * H + j];
    }
    bar_wait(tid, 1u);

    for (int t = 0; t < Tc; ++t) {
        const float* hr = hbuf + (size_t)(t & 1) * Bc * H;        // read buffer
        float*       hw = hbuf + (size_t)((t + 1) & 1) * Bc * H;  // write buffer
        const bool valid = (t < ls[b]);

        // stage h into smem (L2 reads; bypass non-coherent L1)
        for (int idx = tid; idx < Bc * (H / 4); idx += TPB) {
            int bb = idx / (H / 4), kk = idx % (H / 4);
            *(float4*)&hs[bb * Hp + kk * 4] = __ldcg((const float4*)&hr[bb * H + kk * 4]);
        }
        __syncthreads();

        unsigned long long p0 = 0, p1 = 0, p2 = 0, p3 = 0;
        if (valid) {
#pragma unroll 4
            for (int k = kb; k < kb + KS; k += 4) {
                ulonglong2 hv = *(const ulonglong2*)&hrow[k];
                ulonglong2 q0 = *(const ulonglong2*)&w0[k];
                ulonglong2 q1 = *(const ulonglong2*)&w1[k];
                ulonglong2 q2 = *(const ulonglong2*)&w2[k];
                ulonglong2 q3 = *(const ulonglong2*)&w3[k];
                ffma2(p0, hv.x, q0.x); ffma2(p1, hv.x, q1.x);
                ffma2(p2, hv.x, q2.x); ffma2(p3, hv.x, q3.x);
                ffma2(p0, hv.y, q0.y); ffma2(p1, hv.y, q1.y);
                ffma2(p2, hv.y, q2.y); ffma2(p3, hv.y, q3.y);
            }
        }
        if (S > 1) {
            part[tid * 4 + 0] = f2sum(p0); part[tid * 4 + 1] = f2sum(p1);
            part[tid * 4 + 2] = f2sum(p2); part[tid * 4 + 3] = f2sum(p3);
            __syncthreads();
        }
        if (tid < TASKS) {
            float hn;
            if (valid) {
                float a0, a1, a2, a3;
                if (S > 1) {
                    a0 = part[tid * 4 + 0]; a1 = part[tid * 4 + 1];
                    a2 = part[tid * 4 + 2]; a3 = part[tid * 4 + 3];
#pragma unroll
                    for (int s2 = 1; s2 < S; ++s2) {
                        int o = (s2 * TASKS + tid) * 4;
                        a0 += part[o + 0]; a1 += part[o + 1];
                        a2 += part[o + 2]; a3 += part[o + 3];
                    }
                } else {
                    a0 = f2sum(p0); a1 = f2sum(p1); a2 = f2sum(p2); a3 = f2sum(p3);
                }
                float gi = a0 + x0, gf = a1 + x1, gg = a2 + x2, go = a3 + x3;
                float ig = 1.f / (1.f + __expf(-gi));
                float fg = 1.f / (1.f + __expf(-gf));
                float gv = tanhf(gg);
                float og = 1.f / (1.f + __expf(-go));
                float c  = fg * cs[tt] + ig * gv;
                cs[tt] = c;
                hn = og * tanhf(c);
                if (WRITE_Y) yout[((size_t)b * Tc + t) * H + j] = hn;
            } else {
                hn = hrow[j];   // frozen: carry forward staged value
            }
            hw[b * H + j] = hn;
        }

        bar_arrive(tid);
        if (!CONST_IN && sl == 0 && t + 1 < Tc) {   // prefetch next xg while waiting
            const float* xr = &xg[((size_t)b * Tc + t + 1) * 4 * H];
            x0 = xr[0 * H + j]; x1 = xr[1 * H + j];
            x2 = xr[2 * H + j]; x3 = xr[3 * H + j];
        }
        bar_wait(tid, (unsigned)(t + 2));
    }

    if (!WRITE_Y) {   // final frozen h lives in buffer 0 (Tc even)
        for (int idx = tid; idx < Bc * U; idx += TPB) {
            int bb = idx / U, uu = idx % U;
            yout[bb * H + j0 + uu] = hbuf[bb * H + j0 + uu];
        }
    }
}

// -------------------- classifier head --------------------
__global__ void __launch_bounds__(256) head_kernel(
    const float* __restrict__ h0,
    const float* __restrict__ lw1, const float* __restrict__ lb1,
    const float* __restrict__ lw2, const float* __restrict__ lb2,
    float* __restrict__ outp)
{
    __shared__ float hv[512];
    __shared__ float hid[256];
    __shared__ float lg[2];
    int bidx = blockIdx.x, tid = threadIdx.x;
    hv[tid]       = h0[bidx * 512 + tid];
    hv[tid + 256] = h0[bidx * 512 + 256 + tid];
    __syncthreads();
    float acc = lb1[tid];
    const float* wr = &lw1[tid * 512];
#pragma unroll 4
    for (int k = 0; k < 512; k += 4) {
        float4 w = *(const float4*)&wr[k];
        acc += w.x * hv[k] + w.y * hv[k + 1] + w.z * hv[k + 2] + w.w * hv[k + 3];
    }
    hid[tid] = fmaxf(acc, 0.f);
    __syncthreads();
    if (tid < 64) {
        int c = tid >> 5, lane = tid & 31;
        float p = 0.f;
        for (int k = lane; k < 256; k += 32) p += hid[k] * lw2[c * 256 + k];
#pragma unroll
        for (int off = 16; off; off >>= 1) p += __shfl_down_sync(0xffffffffu, p, off);
        if (lane == 0) lg[c] = p + lb2[c];
    }
    __syncthreads();
    if (tid == 0) {
        float m = fmaxf(lg[0], lg[1]);
        float lse = m + logf(expf(lg[0] - m) + expf(lg[1] - m));
        outp[bidx * 2 + 0] = lg[0] - lse;
        outp[bidx * 2 + 1] = lg[1] - lse;
    }
}

// -------------------- launcher --------------------
static inline int lstm_smem_bytes(int H, int U) {
    int Hp = H + 4, R = 4 * U, TASKS = Bc * U;
    return 4 * (R * Hp + Bc * Hp + TASKS + 4 * TPB) + Bc * 4 + 16;
}

extern "C" void kernel_launch(void* const* d_in, const int* in_sizes, int n_in,
                              void* d_out, int out_size) {
    const float* x       = (const float*)d_in[0];
    const int*   lengths = (const int*)  d_in[1];
    const float* e1_wih  = (const float*)d_in[2];
    const float* e1_whh  = (const float*)d_in[3];
    const float* e1_b    = (const float*)d_in[4];
    const float* e2_wih  = (const float*)d_in[5];
    const float* e2_whh  = (const float*)d_in[6];
    const float* e2_b    = (const float*)d_in[7];
    const float* d1_wih  = (const float*)d_in[8];
    const float* d1_whh  = (const float*)d_in[9];
    const float* d1_b    = (const float*)d_in[10];
    const float* d2_wih  = (const float*)d_in[11];
    const float* d2_whh  = (const float*)d_in[12];
    const float* d2_b    = (const float*)d_in[13];
    const float* lw1     = (const float*)d_in[14];
    const float* lb1     = (const float*)d_in[15];
    const float* lw2     = (const float*)d_in[16];
    const float* lb2     = (const float*)d_in[17];
    float* out = (float*)d_out;

    float *xgp, *seqp, *hp, *h0p, *g0p;
    unsigned* syncp;
    cudaGetSymbolAddress((void**)&xgp,  g_xg);
    cudaGetSymbolAddress((void**)&seqp, g_seq);
    cudaGetSymbolAddress((void**)&hp,   g_h);
    cudaGetSymbolAddress((void**)&h0p,  g_h0);
    cudaGetSymbolAddress((void**)&g0p,  g_g0);
    cudaGetSymbolAddress((void**)&syncp, g_sync);

    const int SMEM_E1 = lstm_smem_bytes(256, 2);
    const int SMEM_E2 = lstm_smem_bytes(512, 4);
    const int SMEM_D2 = lstm_smem_bytes(128, 1);
    cudaFuncSetAttribute((const void*)lstm_rec<256, 2, 4, true,  false>,
                         cudaFuncAttributeMaxDynamicSharedMemorySize, SMEM_E1);
    cudaFuncSetAttribute((const void*)lstm_rec<512, 4, 2, false, false>,
                         cudaFuncAttributeMaxDynamicSharedMemorySize, SMEM_E2);
    cudaFuncSetAttribute((const void*)lstm_rec<256, 2, 4, true,  true>,
                         cudaFuncAttributeMaxDynamicSharedMemorySize, SMEM_E1);
    cudaFuncSetAttribute((const void*)lstm_rec<128, 1, 8, true,  false>,
                         cudaFuncAttributeMaxDynamicSharedMemorySize, SMEM_D2);

    const int M = Bc * Tc;
    const size_t SYNC_BYTES = 2 * NGRP * 32 * sizeof(unsigned);

    cudaMemsetAsync(d_out, 0, (size_t)out_size * sizeof(float));

    // encoder 1
    gemm_bias<<<dim3(1024 / 64, M / 64), 256>>>(x, e1_wih, e1_b, xgp, M, 1024, 128, lengths);
    cudaMemsetAsync(syncp, 0, SYNC_BYTES);
    lstm_rec<256, 2, 4, true, false><<<NCTA, TPB, SMEM_E1>>>(xgp, e1_whh, lengths, hp, seqp);

    // encoder 2
    gemm_bias<<<dim3(2048 / 64, M / 64), 256>>>(seqp, e2_wih, e2_b, xgp, M, 2048, 256, lengths);
    cudaMemsetAsync(syncp, 0, SYNC_BYTES);
    lstm_rec<512, 4, 2, false, false><<<NCTA, TPB, SMEM_E2>>>(xgp, e2_whh, lengths, hp, h0p);

    // decoder 1 (constant per-batch input)
    gemm_bias<<<dim3(1024 / 64, 1), 256>>>(h0p, d1_wih, d1_b, g0p, Bc, 1024, 512, nullptr);
    cudaMemsetAsync(syncp, 0, SYNC_BYTES);
    lstm_rec<256, 2, 4, true, true><<<NCTA, TPB, SMEM_E1>>>(g0p, d1_whh, lengths, hp, seqp);

    // decoder 2 -> d_out
    gemm_bias<<<dim3(512 / 64, M / 64), 256>>>(seqp, d2_wih, d2_b, xgp, M, 512, 256, lengths);
    cudaMemsetAsync(syncp, 0, SYNC_BYTES);
    lstm_rec<128, 1, 8, true, false><<<NCTA, TPB, SMEM_D2>>>(xgp, d2_whh, lengths, hp, out);

    // classifier head
    head_kernel<<<Bc, 256>>>(h0p, lw1, lb1, lw2, lb2, out + (size_t)out_size - 2 * Bc);
}